// round 14
// baseline (speedup 1.0000x reference)
#include <cuda_runtime.h>
#include <cuda_fp16.h>
#include <math.h>

#define NN 50000
#define NE 800000
#define DI 128
#define DH 64
#define DOUT 40
#define SLOPE 0.2f
#define SCB 1024
#define NBLK 49            // ceil(50000/1024)

// ---------------- scratch ----------------
__device__ __half2 g_h16[NN * (DH / 2)];     // layer-1 h (fp16)
__device__ __half2 g_h16b[NN * (DOUT / 2)];  // layer-2 h (fp16)
__device__ float   g_as[NN],  g_ad[NN];      // layer-1 att dots
__device__ float   g_as2[NN], g_ad2[NN];     // layer-2 att dots
__device__ int     g_deg[NN];                // starts zero; re-zeroed by scatter
__device__ int     g_rowptr[NN + 1];
__device__ int     g_bsum[NBLK];
__device__ int     g_rank[NE];
__device__ int     g_esrc[NE];

// ---------------- CSR build (self loops handled analytically in agg) --------
__global__ void hist_kernel(const int* __restrict__ ei) {
    int t = blockIdx.x * blockDim.x + threadIdx.x;
    if (t >= NE / 8) return;
    int4 a = *(const int4*)&ei[NE + t * 8];
    int4 b = *(const int4*)&ei[NE + t * 8 + 4];
    int r0 = atomicAdd(&g_deg[a.x], 1);
    int r1 = atomicAdd(&g_deg[a.y], 1);
    int r2 = atomicAdd(&g_deg[a.z], 1);
    int r3 = atomicAdd(&g_deg[a.w], 1);
    int r4 = atomicAdd(&g_deg[b.x], 1);
    int r5 = atomicAdd(&g_deg[b.y], 1);
    int r6 = atomicAdd(&g_deg[b.z], 1);
    int r7 = atomicAdd(&g_deg[b.w], 1);
    *(int4*)&g_rank[t * 8]     = make_int4(r0, r1, r2, r3);
    *(int4*)&g_rank[t * 8 + 4] = make_int4(r4, r5, r6, r7);
}

__global__ void scan_local_kernel() {
    __shared__ int wsum[32];
    int t = threadIdx.x, lane = t & 31, wid = t >> 5;
    int i = blockIdx.x * SCB + t;
    int v = (i < NN) ? g_deg[i] : 0;
    int sc = v;
#pragma unroll
    for (int off = 1; off < 32; off <<= 1) {
        int u = __shfl_up_sync(0xffffffffu, sc, off);
        if (lane >= off) sc += u;
    }
    if (lane == 31) wsum[wid] = sc;
    __syncthreads();
    if (wid == 0) {
        int w0 = wsum[lane];
        int s = w0;
#pragma unroll
        for (int off = 1; off < 32; off <<= 1) {
            int u = __shfl_up_sync(0xffffffffu, s, off);
            if (lane >= off) s += u;
        }
        wsum[lane] = s - w0;
    }
    __syncthreads();
    int ex = sc - v + wsum[wid];
    if (i < NN) g_rowptr[i] = ex;
    if (t == SCB - 1) g_bsum[blockIdx.x] = ex + v;
}

__global__ void add_off_kernel() {
    __shared__ int sh[2];
    int t = threadIdx.x, bid = blockIdx.x;
    if (t < 32) {
        int a = (t < NBLK) ? g_bsum[t] : 0;
        int b = (t + 32 < NBLK) ? g_bsum[t + 32] : 0;
        int pa = ((t < bid) ? a : 0) + ((t + 32 < bid) ? b : 0);
        int ta = a + b;
#pragma unroll
        for (int off = 16; off; off >>= 1) {
            pa += __shfl_xor_sync(0xffffffffu, pa, off);
            ta += __shfl_xor_sync(0xffffffffu, ta, off);
        }
        if (t == 0) { sh[0] = pa; sh[1] = ta; }
    }
    __syncthreads();
    int pre = sh[0];
    int i = bid * SCB + t;
    if (i < NN) g_rowptr[i] += pre;
    if (bid == NBLK - 1 && t == 0) g_rowptr[NN] = sh[1];
}

__global__ void scatter_kernel(const int* __restrict__ ei) {
    int t = blockIdx.x * blockDim.x + threadIdx.x;
    if (t < NE / 8) {
        int4 s0 = *(const int4*)&ei[t * 8];
        int4 s1 = *(const int4*)&ei[t * 8 + 4];
        int4 d0 = *(const int4*)&ei[NE + t * 8];
        int4 d1 = *(const int4*)&ei[NE + t * 8 + 4];
        int4 r0 = *(const int4*)&g_rank[t * 8];
        int4 r1 = *(const int4*)&g_rank[t * 8 + 4];
        g_esrc[g_rowptr[d0.x] + r0.x] = s0.x;
        g_esrc[g_rowptr[d0.y] + r0.y] = s0.y;
        g_esrc[g_rowptr[d0.z] + r0.z] = s0.z;
        g_esrc[g_rowptr[d0.w] + r0.w] = s0.w;
        g_esrc[g_rowptr[d1.x] + r1.x] = s1.x;
        g_esrc[g_rowptr[d1.y] + r1.y] = s1.y;
        g_esrc[g_rowptr[d1.z] + r1.z] = s1.z;
        g_esrc[g_rowptr[d1.w] + r1.w] = s1.w;
    }
    int stride = gridDim.x * blockDim.x;
    for (int i = t; i < NN; i += stride) g_deg[i] = 0;
}

// ---------------- gemm1: all-smem operands, 64-node x 64-col tile -----------
// 256 threads: thread = (ng = tid>>4) node group of 4, (c4 = tid&15) col group of 4.
// Per 4-k chunk: 4 LDS.128 x (2-way bcast) + 4 LDS.128 W + 64 FFMA. No mainloop LDG.
__global__ __launch_bounds__(256)
void gemm1_kernel(const float* __restrict__ X, const float* __restrict__ W,
                  const float* __restrict__ asrc, const float* __restrict__ adst) {
    extern __shared__ float sm[];
    float* sxn = sm;                 // [64][128] node-major x
    float* sw  = sm + 64 * DI;       // [128][64] k-major W
    int tid = threadIdx.x;
    int base = blockIdx.x * 64;

    for (int i = tid; i < 64 * (DI / 4); i += 256) {
        int node = base + (i >> 5);
        float4 v = (node < NN) ? ((const float4*)X)[(size_t)node * (DI / 4) + (i & 31)]
                               : make_float4(0.f, 0.f, 0.f, 0.f);
        ((float4*)sxn)[i] = v;
    }
    for (int i = tid; i < DI * DH / 4; i += 256)
        ((float4*)sw)[i] = ((const float4*)W)[i];
    __syncthreads();

    int c4 = tid & 15, ng = tid >> 4;
    const float4* sx4 = (const float4*)sxn;
    const float4* sw4 = (const float4*)sw;
    float acc[4][4];
#pragma unroll
    for (int n = 0; n < 4; n++)
#pragma unroll
        for (int c = 0; c < 4; c++) acc[n][c] = 0.f;

#pragma unroll 4
    for (int kc = 0; kc < DI / 4; kc++) {
        float4 xv[4];
#pragma unroll
        for (int n = 0; n < 4; n++) xv[n] = sx4[(ng * 4 + n) * (DI / 4) + kc];
#pragma unroll
        for (int j = 0; j < 4; j++) {
            float4 wv = sw4[(kc * 4 + j) * (DH / 4) + c4];
#pragma unroll
            for (int n = 0; n < 4; n++) {
                float xs = (j == 0) ? xv[n].x : (j == 1) ? xv[n].y : (j == 2) ? xv[n].z : xv[n].w;
                acc[n][0] += xs * wv.x;
                acc[n][1] += xs * wv.y;
                acc[n][2] += xs * wv.z;
                acc[n][3] += xs * wv.w;
            }
        }
    }
    __syncthreads();

    float* hacc = sxn;               // reuse as h tile [64][64]
#pragma unroll
    for (int n = 0; n < 4; n++) {
        float4 v = make_float4(acc[n][0], acc[n][1], acc[n][2], acc[n][3]);
        ((float4*)hacc)[(ng * 4 + n) * (DH / 4) + c4] = v;
    }
    __syncthreads();

    // fp16 conversion (coalesced half2 stores)
    for (int idx = tid; idx < 64 * (DH / 2); idx += 256) {
        int node = idx / (DH / 2), c = idx % (DH / 2);
        if (base + node < NN) {
            float2 v = make_float2(hacc[node * DH + 2 * c], hacc[node * DH + 2 * c + 1]);
            g_h16[(size_t)(base + node) * (DH / 2) + c] = __float22half2_rn(v);
        }
    }
    // att dots: warp per node; att vectors hoisted per lane
    int w = tid >> 5, lane = tid & 31;
    float a0 = asrc[lane], a1 = asrc[lane + 32];
    float d0 = adst[lane], d1 = adst[lane + 32];
    for (int node = w; node < 64; node += 8) {
        float h0 = hacc[node * DH + lane], h1 = hacc[node * DH + lane + 32];
        float sa = h0 * a0 + h1 * a1;
        float sd = h0 * d0 + h1 * d1;
#pragma unroll
        for (int off = 16; off; off >>= 1) {
            sa += __shfl_down_sync(0xffffffffu, sa, off);
            sd += __shfl_down_sync(0xffffffffu, sd, off);
        }
        if (lane == 0 && base + node < NN) {
            g_as[base + node] = sa;
            g_ad[base + node] = sd;
        }
    }
}

// ---------------- agg_mid: layer-1 softmax-agg + FUSED gemm2/att2 ------------
// Grid-stride over nodes; warp per node. Epilogue computes h2 = relu(h1)@W2,
// att2 dots, writes g_h16b / g_as2 / g_ad2. W2 preloaded to smem per block.
__global__ __launch_bounds__(256)
void agg_mid_kernel(const float* __restrict__ b1, const float* __restrict__ W2,
                    const float* __restrict__ as2, const float* __restrict__ ad2) {
    __shared__ float  sp_p[8][32];
    __shared__ int    sp_s[8][32];
    __shared__ float  sh1[8][DH];
    __shared__ float2 sw2[DH * (DOUT / 2)];
    int tid = threadIdx.x, wl = tid >> 5, lane = tid & 31;

    for (int i = tid; i < DH * (DOUT / 2); i += 256)
        sw2[i] = ((const float2*)W2)[i];
    __syncthreads();

    // per-lane hoists
    float bb0 = b1[2 * lane], bb1 = b1[2 * lane + 1];            // lane<32, DH=64
    float asx = 0.f, asy = 0.f, adx = 0.f, ady = 0.f;
    if (lane < DOUT / 2) {
        asx = as2[2 * lane]; asy = as2[2 * lane + 1];
        adx = ad2[2 * lane]; ady = ad2[2 * lane + 1];
    }

    for (int w = blockIdx.x * 8 + wl; w < NN; w += gridDim.x * 8) {
        int beg = g_rowptr[w];
        int end = g_rowptr[w + 1];
        float ad_n = g_ad[w];

        float es = g_as[w] + ad_n;
        es = es > 0.f ? es : SLOPE * es;
        float m = es;
        float ssum = (lane == 0) ? 1.f : 0.f;
        float2 hw = __half22float2(g_h16[(size_t)w * (DH / 2) + lane]);
        float ax = hw.x, ay = hw.y;

        for (int j0 = beg; j0 < end; j0 += 32) {
            int j = j0 + lane;
            int s = 0;
            float e = -INFINITY;
            if (j < end) {
                s = g_esrc[j];
                e = g_as[s] + ad_n;
                e = e > 0.f ? e : SLOPE * e;
            }
            float tm = e;
#pragma unroll
            for (int off = 16; off; off >>= 1) tm = fmaxf(tm, __shfl_xor_sync(0xffffffffu, tm, off));
            float mnew = fmaxf(m, tm);
            float scale = __expf(m - mnew);
            ssum *= scale; ax *= scale; ay *= scale;
            m = mnew;

            float p = (j < end) ? __expf(e - m) : 0.f;
            ssum += p;
            sp_p[wl][lane] = p;
            sp_s[wl][lane] = s;
            __syncwarp();
            int cnt = min(32, end - j0);
#pragma unroll 8
            for (int k = 0; k < cnt; k++) {
                float pk = sp_p[wl][k];
                int   sk = sp_s[wl][k];
                float2 hv = __half22float2(g_h16[(size_t)sk * (DH / 2) + lane]);
                ax += pk * hv.x;
                ay += pk * hv.y;
            }
            __syncwarp();
        }
#pragma unroll
        for (int off = 16; off; off >>= 1) ssum += __shfl_xor_sync(0xffffffffu, ssum, off);
        float inv = 1.f / (ssum + 1e-16f);

        // h1 row (relu + bias), staged to smem
        float v0 = fmaxf(ax * inv + bb0, 0.f);
        float v1 = fmaxf(ay * inv + bb1, 0.f);
        sh1[wl][2 * lane]     = v0;
        sh1[wl][2 * lane + 1] = v1;
        __syncwarp();

        // fused gemm2: h2 col pair per lane
        float h2x = 0.f, h2y = 0.f;
        if (lane < DOUT / 2) {
#pragma unroll 16
            for (int k = 0; k < DH; k++) {
                float xk = sh1[wl][k];
                float2 wv = sw2[k * (DOUT / 2) + lane];
                h2x += xk * wv.x;
                h2y += xk * wv.y;
            }
        }
        float sa = (lane < DOUT / 2) ? (h2x * asx + h2y * asy) : 0.f;
        float sd = (lane < DOUT / 2) ? (h2x * adx + h2y * ady) : 0.f;
#pragma unroll
        for (int off = 16; off; off >>= 1) {
            sa += __shfl_down_sync(0xffffffffu, sa, off);
            sd += __shfl_down_sync(0xffffffffu, sd, off);
        }
        if (lane < DOUT / 2)
            g_h16b[(size_t)w * (DOUT / 2) + lane] = __float22half2_rn(make_float2(h2x, h2y));
        if (lane == 0) { g_as2[w] = sa; g_ad2[w] = sd; }
        __syncwarp();           // sh1 safe to reuse next iteration
    }
}

// ---------------- agg_final: layer-2 softmax-agg + log_softmax ---------------
__global__ void agg_final_kernel(const float* __restrict__ b2, float* __restrict__ out) {
    __shared__ float sp_p[8][32];
    __shared__ int   sp_s[8][32];
    int wl = threadIdx.x >> 5;
    int w = (blockIdx.x * blockDim.x + threadIdx.x) >> 5;
    int lane = threadIdx.x & 31;
    if (w >= NN) return;
    int beg = g_rowptr[w];
    int end = g_rowptr[w + 1];
    float ad_n = g_ad2[w];

    float bb0 = 0.f, bb1 = 0.f;
    if (lane < DOUT / 2) { bb0 = b2[2 * lane]; bb1 = b2[2 * lane + 1]; }

    float es = g_as2[w] + ad_n;
    es = es > 0.f ? es : SLOPE * es;
    float m = es;
    float ssum = (lane == 0) ? 1.f : 0.f;
    float ax = 0.f, ay = 0.f;
    if (lane < DOUT / 2) {
        float2 hw = __half22float2(g_h16b[(size_t)w * (DOUT / 2) + lane]);
        ax = hw.x; ay = hw.y;
    }

    for (int j0 = beg; j0 < end; j0 += 32) {
        int j = j0 + lane;
        int s = 0;
        float e = -INFINITY;
        if (j < end) {
            s = g_esrc[j];
            e = g_as2[s] + ad_n;
            e = e > 0.f ? e : SLOPE * e;
        }
        float tm = e;
#pragma unroll
        for (int off = 16; off; off >>= 1) tm = fmaxf(tm, __shfl_xor_sync(0xffffffffu, tm, off));
        float mnew = fmaxf(m, tm);
        float scale = __expf(m - mnew);
        ssum *= scale; ax *= scale; ay *= scale;
        m = mnew;

        float p = (j < end) ? __expf(e - m) : 0.f;
        ssum += p;
        sp_p[wl][lane] = p;
        sp_s[wl][lane] = s;
        __syncwarp();
        int cnt = min(32, end - j0);
        if (lane < DOUT / 2) {
#pragma unroll 8
            for (int k = 0; k < cnt; k++) {
                float pk = sp_p[wl][k];
                int   sk = sp_s[wl][k];
                float2 hv = __half22float2(g_h16b[(size_t)sk * (DOUT / 2) + lane]);
                ax += pk * hv.x;
                ay += pk * hv.y;
            }
        }
        __syncwarp();
    }
#pragma unroll
    for (int off = 16; off; off >>= 1) ssum += __shfl_xor_sync(0xffffffffu, ssum, off);
    float inv = 1.f / (ssum + 1e-16f);

    float va = -INFINITY, vb = -INFINITY;
    if (lane < DOUT / 2) {
        va = ax * inv + bb0;
        vb = ay * inv + bb1;
    }
    float mx = fmaxf(va, vb);
#pragma unroll
    for (int off = 16; off; off >>= 1) mx = fmaxf(mx, __shfl_xor_sync(0xffffffffu, mx, off));
    float se = (lane < DOUT / 2) ? (__expf(va - mx) + __expf(vb - mx)) : 0.f;
#pragma unroll
    for (int off = 16; off; off >>= 1) se += __shfl_xor_sync(0xffffffffu, se, off);
    float lse = mx + logf(se);
    if (lane < DOUT / 2) {
        float2 o;
        o.x = va - lse;
        o.y = vb - lse;
        ((float2*)out)[(size_t)w * (DOUT / 2) + lane] = o;
    }
}

extern "C" void kernel_launch(void* const* d_in, const int* in_sizes, int n_in,
                              void* d_out, int out_size) {
    const float* x   = (const float*)d_in[0];
    const int*   ei  = (const int*)d_in[1];
    const float* W1  = (const float*)d_in[2];
    const float* as1 = (const float*)d_in[3];
    const float* ad1 = (const float*)d_in[4];
    const float* b1  = (const float*)d_in[5];
    const float* W2  = (const float*)d_in[6];
    const float* as2 = (const float*)d_in[7];
    const float* ad2 = (const float*)d_in[8];
    const float* b2  = (const float*)d_in[9];
    float* out = (float*)d_out;

    static cudaStream_t s2 = nullptr;
    static cudaEvent_t evFork = nullptr, evCSR = nullptr;
    if (!s2) {
        cudaStreamCreateWithFlags(&s2, cudaStreamNonBlocking);
        cudaEventCreateWithFlags(&evFork, cudaEventDisableTiming);
        cudaEventCreateWithFlags(&evCSR, cudaEventDisableTiming);
        cudaFuncSetAttribute(gemm1_kernel,
                             cudaFuncAttributeMaxDynamicSharedMemorySize,
                             (64 * DI + DI * DH) * (int)sizeof(float));
    }

    const int TB = 256;
    int grid_edges = (NE / 8 + TB - 1) / TB;        // 391
    int grid_warp_nodes = (NN * 32 + TB - 1) / TB;  // 6250
    int grid_nodes64 = (NN + 63) / 64;              // 782
    const int SM1 = (64 * DI + DI * DH) * (int)sizeof(float);   // 64KB

    // fork: CSR build on s2 concurrent with gemm1 on main (gemm1 = 4th launch)
    cudaEventRecord(evFork, 0);
    cudaStreamWaitEvent(s2, evFork, 0);

    hist_kernel<<<grid_edges, TB, 0, s2>>>(ei);                       // 1
    scan_local_kernel<<<NBLK, SCB, 0, s2>>>();                        // 2
    add_off_kernel<<<NBLK, SCB, 0, s2>>>();                           // 3
    gemm1_kernel<<<grid_nodes64, 256, SM1>>>(x, W1, as1, ad1);        // 4 (main)
    scatter_kernel<<<grid_edges, TB, 0, s2>>>(ei);                    // 5
    cudaEventRecord(evCSR, s2);

    cudaStreamWaitEvent(0, evCSR, 0);
    agg_mid_kernel<<<1184, 256>>>(b1, W2, as2, ad2);                  // 6
    agg_final_kernel<<<grid_warp_nodes, TB>>>(b2, out);               // 7
}

// round 15
// speedup vs baseline: 1.0750x; 1.0750x over previous
#include <cuda_runtime.h>
#include <cuda_fp16.h>
#include <math.h>

#define NN 50000
#define NE 800000
#define DI 128
#define DH 64
#define DOUT 40
#define SLOPE 0.2f
#define SCB 1024
#define NBLK 49            // ceil(50000/1024)

// ---------------- scratch ----------------
__device__ __half2 g_h16[NN * (DH / 2)];     // h fp16 (layer2 reuses, DOUT/2 layout)
__device__ float   g_as[NN], g_ad[NN];
__device__ float   g_h1o[NN * DH];
__device__ float   g_maxas1 = -3.0e38f;      // global max of as (layer 1)
__device__ float   g_maxas2 = -3.0e38f;      // global max of as (layer 2)
__device__ int     g_deg[NN];                // starts zero; re-zeroed by scatter
__device__ int     g_rowptr[NN + 1];
__device__ int     g_bsum[NBLK];
__device__ int     g_rank[NE];
__device__ int     g_esrc[NE];

__device__ __forceinline__ void atomicMaxF(float* a, float v) {
    if (v >= 0.f) atomicMax((int*)a, __float_as_int(v));
    else atomicMin((unsigned int*)a, __float_as_uint(v));
}

// ---------------- CSR build (self loops handled analytically in agg) --------
__global__ void hist_kernel(const int* __restrict__ ei) {
    int t = blockIdx.x * blockDim.x + threadIdx.x;
    if (t >= NE / 8) return;
    int4 a = *(const int4*)&ei[NE + t * 8];
    int4 b = *(const int4*)&ei[NE + t * 8 + 4];
    int r0 = atomicAdd(&g_deg[a.x], 1);
    int r1 = atomicAdd(&g_deg[a.y], 1);
    int r2 = atomicAdd(&g_deg[a.z], 1);
    int r3 = atomicAdd(&g_deg[a.w], 1);
    int r4 = atomicAdd(&g_deg[b.x], 1);
    int r5 = atomicAdd(&g_deg[b.y], 1);
    int r6 = atomicAdd(&g_deg[b.z], 1);
    int r7 = atomicAdd(&g_deg[b.w], 1);
    *(int4*)&g_rank[t * 8]     = make_int4(r0, r1, r2, r3);
    *(int4*)&g_rank[t * 8 + 4] = make_int4(r4, r5, r6, r7);
}

__global__ void scan_local_kernel() {
    __shared__ int wsum[32];
    int t = threadIdx.x, lane = t & 31, wid = t >> 5;
    int i = blockIdx.x * SCB + t;
    int v = (i < NN) ? g_deg[i] : 0;
    int sc = v;
#pragma unroll
    for (int off = 1; off < 32; off <<= 1) {
        int u = __shfl_up_sync(0xffffffffu, sc, off);
        if (lane >= off) sc += u;
    }
    if (lane == 31) wsum[wid] = sc;
    __syncthreads();
    if (wid == 0) {
        int w0 = wsum[lane];
        int s = w0;
#pragma unroll
        for (int off = 1; off < 32; off <<= 1) {
            int u = __shfl_up_sync(0xffffffffu, s, off);
            if (lane >= off) s += u;
        }
        wsum[lane] = s - w0;
    }
    __syncthreads();
    int ex = sc - v + wsum[wid];
    if (i < NN) g_rowptr[i] = ex;
    if (t == SCB - 1) g_bsum[blockIdx.x] = ex + v;
}

__global__ void add_off_kernel() {
    __shared__ int sh[2];
    int t = threadIdx.x, bid = blockIdx.x;
    if (t < 32) {
        int a = (t < NBLK) ? g_bsum[t] : 0;
        int b = (t + 32 < NBLK) ? g_bsum[t + 32] : 0;
        int pa = ((t < bid) ? a : 0) + ((t + 32 < bid) ? b : 0);
        int ta = a + b;
#pragma unroll
        for (int off = 16; off; off >>= 1) {
            pa += __shfl_xor_sync(0xffffffffu, pa, off);
            ta += __shfl_xor_sync(0xffffffffu, ta, off);
        }
        if (t == 0) { sh[0] = pa; sh[1] = ta; }
    }
    __syncthreads();
    int pre = sh[0];
    int i = bid * SCB + t;
    if (i < NN) g_rowptr[i] += pre;
    if (bid == NBLK - 1 && t == 0) g_rowptr[NN] = sh[1];
}

__global__ void scatter_kernel(const int* __restrict__ ei) {
    int t = blockIdx.x * blockDim.x + threadIdx.x;
    if (t < NE / 8) {
        int4 s0 = *(const int4*)&ei[t * 8];
        int4 s1 = *(const int4*)&ei[t * 8 + 4];
        int4 d0 = *(const int4*)&ei[NE + t * 8];
        int4 d1 = *(const int4*)&ei[NE + t * 8 + 4];
        int4 r0 = *(const int4*)&g_rank[t * 8];
        int4 r1 = *(const int4*)&g_rank[t * 8 + 4];
        g_esrc[g_rowptr[d0.x] + r0.x] = s0.x;
        g_esrc[g_rowptr[d0.y] + r0.y] = s0.y;
        g_esrc[g_rowptr[d0.z] + r0.z] = s0.z;
        g_esrc[g_rowptr[d0.w] + r0.w] = s0.w;
        g_esrc[g_rowptr[d1.x] + r1.x] = s1.x;
        g_esrc[g_rowptr[d1.y] + r1.y] = s1.y;
        g_esrc[g_rowptr[d1.z] + r1.z] = s1.z;
        g_esrc[g_rowptr[d1.w] + r1.w] = s1.w;
    }
    int stride = gridDim.x * blockDim.x;
    for (int i = t; i < NN; i += stride) g_deg[i] = 0;
}

// ---------------- gemm1: all-smem operands, 64x64 tile; emits maxas1 --------
__global__ __launch_bounds__(256)
void gemm1_kernel(const float* __restrict__ X, const float* __restrict__ W,
                  const float* __restrict__ asrc, const float* __restrict__ adst) {
    extern __shared__ float sm[];
    float* sxn = sm;                 // [64][128] node-major x
    float* sw  = sm + 64 * DI;       // [128][64] k-major W
    __shared__ float smax[8];
    int tid = threadIdx.x;
    int base = blockIdx.x * 64;
    if (blockIdx.x == 0 && tid == 0) g_maxas2 = -3.0e38f;   // reset for this call's gemm2

    for (int i = tid; i < 64 * (DI / 4); i += 256) {
        int node = base + (i >> 5);
        float4 v = (node < NN) ? ((const float4*)X)[(size_t)node * (DI / 4) + (i & 31)]
                               : make_float4(0.f, 0.f, 0.f, 0.f);
        ((float4*)sxn)[i] = v;
    }
    for (int i = tid; i < DI * DH / 4; i += 256)
        ((float4*)sw)[i] = ((const float4*)W)[i];
    __syncthreads();

    int c4 = tid & 15, ng = tid >> 4;
    const float4* sx4 = (const float4*)sxn;
    const float4* sw4 = (const float4*)sw;
    float acc[4][4];
#pragma unroll
    for (int n = 0; n < 4; n++)
#pragma unroll
        for (int c = 0; c < 4; c++) acc[n][c] = 0.f;

#pragma unroll 4
    for (int kc = 0; kc < DI / 4; kc++) {
        float4 xv[4];
#pragma unroll
        for (int n = 0; n < 4; n++) xv[n] = sx4[(ng * 4 + n) * (DI / 4) + kc];
#pragma unroll
        for (int j = 0; j < 4; j++) {
            float4 wv = sw4[(kc * 4 + j) * (DH / 4) + c4];
#pragma unroll
            for (int n = 0; n < 4; n++) {
                float xs = (j == 0) ? xv[n].x : (j == 1) ? xv[n].y : (j == 2) ? xv[n].z : xv[n].w;
                acc[n][0] += xs * wv.x;
                acc[n][1] += xs * wv.y;
                acc[n][2] += xs * wv.z;
                acc[n][3] += xs * wv.w;
            }
        }
    }
    __syncthreads();

    float* hacc = sxn;               // reuse as h tile [64][64]
#pragma unroll
    for (int n = 0; n < 4; n++)
        ((float4*)hacc)[(ng * 4 + n) * (DH / 4) + c4] =
            make_float4(acc[n][0], acc[n][1], acc[n][2], acc[n][3]);
    __syncthreads();

    for (int idx = tid; idx < 64 * (DH / 2); idx += 256) {
        int node = idx / (DH / 2), c = idx % (DH / 2);
        if (base + node < NN) {
            float2 v = make_float2(hacc[node * DH + 2 * c], hacc[node * DH + 2 * c + 1]);
            g_h16[(size_t)(base + node) * (DH / 2) + c] = __float22half2_rn(v);
        }
    }
    int w = tid >> 5, lane = tid & 31;
    float a0 = asrc[lane], a1 = asrc[lane + 32];
    float d0 = adst[lane], d1 = adst[lane + 32];
    float wmax = -3.0e38f;
    for (int node = w; node < 64; node += 8) {
        float h0 = hacc[node * DH + lane], h1 = hacc[node * DH + lane + 32];
        float sa = h0 * a0 + h1 * a1;
        float sd = h0 * d0 + h1 * d1;
#pragma unroll
        for (int off = 16; off; off >>= 1) {
            sa += __shfl_down_sync(0xffffffffu, sa, off);
            sd += __shfl_down_sync(0xffffffffu, sd, off);
        }
        if (lane == 0 && base + node < NN) {
            g_as[base + node] = sa;
            g_ad[base + node] = sd;
            wmax = fmaxf(wmax, sa);
        }
    }
    if (lane == 0) smax[w] = wmax;
    __syncthreads();
    if (tid == 0) {
        float mm = smax[0];
#pragma unroll
        for (int i = 1; i < 8; i++) mm = fmaxf(mm, smax[i]);
        atomicMaxF(&g_maxas1, mm);
    }
}

// ---------------- gemm2 + att2 (round-13 style, smem x-tile); emits maxas2 --
template <int Din, int Dout>
__global__ void gemm_att_kernel(const float* __restrict__ W,
                                const float* __restrict__ asrc,
                                const float* __restrict__ adst) {
    __shared__ float sx[32 * Din];
    __shared__ float smax[(Dout * 4) / 32];
    int base = blockIdx.x * 32;
    int tid = threadIdx.x;
    const int nthr = Dout * 4;
    if (blockIdx.x == 0 && tid == 0) g_maxas1 = -3.0e38f;   // dead after agg1; reset for next call

    for (int i = tid; i < 32 * (Din / 4); i += nthr) {
        int node = base + i / (Din / 4);
        float4 v = (node < NN) ? ((const float4*)g_h1o)[(size_t)node * (Din / 4) + (i % (Din / 4))]
                               : make_float4(0.f, 0.f, 0.f, 0.f);
        ((float4*)sx)[i] = v;
    }
    __syncthreads();

    int j = tid % Dout;
    int n0 = tid / Dout;
    float acc[8];
#pragma unroll
    for (int i = 0; i < 8; i++) acc[i] = 0.f;

    for (int k = 0; k < Din; k += 4) {
        float w0 = W[(k + 0) * Dout + j];
        float w1 = W[(k + 1) * Dout + j];
        float w2 = W[(k + 2) * Dout + j];
        float w3 = W[(k + 3) * Dout + j];
#pragma unroll
        for (int i = 0; i < 8; i++) {
            int node = n0 + i * 4;
            float4 xv = ((const float4*)sx)[node * (Din / 4) + (k >> 2)];
            acc[i] += xv.x * w0 + xv.y * w1 + xv.z * w2 + xv.w * w3;
        }
    }
    __syncthreads();

    float* hacc = sx;
#pragma unroll
    for (int i = 0; i < 8; i++) hacc[(n0 + i * 4) * Dout + j] = acc[i];
    __syncthreads();

    for (int idx = tid; idx < 32 * (Dout / 2); idx += nthr) {
        int node = idx / (Dout / 2), c = idx % (Dout / 2);
        if (base + node < NN) {
            float2 v = make_float2(hacc[node * Dout + 2 * c], hacc[node * Dout + 2 * c + 1]);
            g_h16[(size_t)(base + node) * (Dout / 2) + c] = __float22half2_rn(v);
        }
    }

    int wid = tid >> 5, lane = tid & 31, nw = nthr / 32;
    float wmax = -3.0e38f;
    for (int node = wid; node < 32; node += nw) {
        float sa = 0.f, sd = 0.f;
        for (int c = lane; c < Dout; c += 32) {
            float h = hacc[node * Dout + c];
            sa += h * asrc[c];
            sd += h * adst[c];
        }
#pragma unroll
        for (int off = 16; off; off >>= 1) {
            sa += __shfl_down_sync(0xffffffffu, sa, off);
            sd += __shfl_down_sync(0xffffffffu, sd, off);
        }
        if (lane == 0 && base + node < NN) {
            g_as[base + node] = sa;
            g_ad[base + node] = sd;
            wmax = fmaxf(wmax, sa);
        }
    }
    if (lane == 0) smax[wid] = wmax;
    __syncthreads();
    if (tid == 0) {
        float mm = smax[0];
#pragma unroll
        for (int i = 1; i < nthr / 32; i++) mm = fmaxf(mm, smax[i]);
        atomicMaxF(&g_maxas2, mm);
    }
}

// ---------------- bound-stabilized softmax aggregation (+epilogue) ----------
// K_n = leaky(maxAS + ad_n) >= every e for this node (leaky monotone).
// No per-tile max reduction, no online rescale. Self loop folded into init.
template <int D, bool FINAL>
__global__ void agg_kernel(const float* __restrict__ b, float* __restrict__ out) {
    __shared__ float sp_p[8][32];
    __shared__ int   sp_s[8][32];
    int wl = threadIdx.x >> 5;
    int w = (blockIdx.x * blockDim.x + threadIdx.x) >> 5;
    int lane = threadIdx.x & 31;
    if (w >= NN) return;
    int beg = g_rowptr[w];
    int end = g_rowptr[w + 1];
    float ad_n = g_ad[w];
    float maxas = FINAL ? g_maxas2 : g_maxas1;
    float K = maxas + ad_n;
    K = K > 0.f ? K : SLOPE * K;

    // self edge
    float es = g_as[w] + ad_n;
    es = es > 0.f ? es : SLOPE * es;
    float ps = __expf(es - K);
    float ssum = (lane == 0) ? ps : 0.f;
    float ax = 0.f, ay = 0.f;
    if (lane < D / 2) {
        float2 hw = __half22float2(g_h16[(size_t)w * (D / 2) + lane]);
        ax = ps * hw.x; ay = ps * hw.y;
    }

    for (int j0 = beg; j0 < end; j0 += 32) {
        int j = j0 + lane;
        int s = 0;
        float p = 0.f;
        if (j < end) {
            s = g_esrc[j];
            float e = g_as[s] + ad_n;
            e = e > 0.f ? e : SLOPE * e;
            p = __expf(e - K);
        }
        ssum += p;
        sp_p[wl][lane] = p;
        sp_s[wl][lane] = s;
        __syncwarp();
        int cnt = min(32, end - j0);
        if (lane < D / 2) {
#pragma unroll 8
            for (int k = 0; k < cnt; k++) {
                float pk = sp_p[wl][k];
                int   sk = sp_s[wl][k];
                float2 hv = __half22float2(g_h16[(size_t)sk * (D / 2) + lane]);
                ax += pk * hv.x;
                ay += pk * hv.y;
            }
        }
        __syncwarp();
    }
#pragma unroll
    for (int off = 16; off; off >>= 1) ssum += __shfl_xor_sync(0xffffffffu, ssum, off);
    float inv = 1.f / (ssum + 1e-16f);

    if (!FINAL) {
        float v0 = fmaxf(ax * inv + b[2 * lane], 0.f);
        float v1 = fmaxf(ay * inv + b[2 * lane + 1], 0.f);
        ((float2*)g_h1o)[(size_t)w * (D / 2) + lane] = make_float2(v0, v1);
    } else {
        float va = -INFINITY, vb = -INFINITY;
        if (lane < D / 2) {
            va = ax * inv + b[2 * lane];
            vb = ay * inv + b[2 * lane + 1];
        }
        float mx = fmaxf(va, vb);
#pragma unroll
        for (int off = 16; off; off >>= 1) mx = fmaxf(mx, __shfl_xor_sync(0xffffffffu, mx, off));
        float se = (lane < D / 2) ? (__expf(va - mx) + __expf(vb - mx)) : 0.f;
#pragma unroll
        for (int off = 16; off; off >>= 1) se += __shfl_xor_sync(0xffffffffu, se, off);
        float lse = mx + logf(se);
        if (lane < D / 2) {
            float2 o;
            o.x = va - lse;
            o.y = vb - lse;
            ((float2*)out)[(size_t)w * (D / 2) + lane] = o;
        }
    }
}

extern "C" void kernel_launch(void* const* d_in, const int* in_sizes, int n_in,
                              void* d_out, int out_size) {
    const float* x   = (const float*)d_in[0];
    const int*   ei  = (const int*)d_in[1];
    const float* W1  = (const float*)d_in[2];
    const float* as1 = (const float*)d_in[3];
    const float* ad1 = (const float*)d_in[4];
    const float* b1  = (const float*)d_in[5];
    const float* W2  = (const float*)d_in[6];
    const float* as2 = (const float*)d_in[7];
    const float* ad2 = (const float*)d_in[8];
    const float* b2  = (const float*)d_in[9];
    float* out = (float*)d_out;

    static cudaStream_t s2 = nullptr;
    static cudaEvent_t evFork = nullptr, evCSR = nullptr;
    if (!s2) {
        cudaStreamCreateWithFlags(&s2, cudaStreamNonBlocking);
        cudaEventCreateWithFlags(&evFork, cudaEventDisableTiming);
        cudaEventCreateWithFlags(&evCSR, cudaEventDisableTiming);
        cudaFuncSetAttribute(gemm1_kernel,
                             cudaFuncAttributeMaxDynamicSharedMemorySize,
                             (64 * DI + DI * DH) * (int)sizeof(float));
    }

    const int TB = 256;
    int grid_edges = (NE / 8 + TB - 1) / TB;        // 391
    int grid_warp_nodes = (NN * 32 + TB - 1) / TB;  // 6250
    int grid_nodes64 = (NN + 63) / 64;              // 782
    int grid_nodes32 = (NN + 31) / 32;              // 1563
    const int SM1 = (64 * DI + DI * DH) * (int)sizeof(float);   // 64KB

    // fork: CSR build on s2 concurrent with gemm1 on main (gemm1 = 4th launch)
    cudaEventRecord(evFork, 0);
    cudaStreamWaitEvent(s2, evFork, 0);

    hist_kernel<<<grid_edges, TB, 0, s2>>>(ei);                       // 1
    scan_local_kernel<<<NBLK, SCB, 0, s2>>>();                        // 2
    add_off_kernel<<<NBLK, SCB, 0, s2>>>();                           // 3
    gemm1_kernel<<<grid_nodes64, 256, SM1>>>(x, W1, as1, ad1);        // 4 (main)
    scatter_kernel<<<grid_edges, TB, 0, s2>>>(ei);                    // 5
    cudaEventRecord(evCSR, s2);

    cudaStreamWaitEvent(0, evCSR, 0);
    agg_kernel<DH, false><<<grid_warp_nodes, TB>>>(b1, nullptr);      // 6
    gemm_att_kernel<DH, DOUT><<<grid_nodes32, DOUT * 4>>>(W2, as2, ad2); // 7
    agg_kernel<DOUT, true><<<grid_warp_nodes, TB>>>(b2, out);         // 8
}